// round 1
// baseline (speedup 1.0000x reference)
#include <cuda_runtime.h>
#include <math.h>

// Problem constants (match reference)
#define NCLS   20
#define NANC   5
#define NBATCH 64
#define NH_    38
#define NW_    38
#define MAXB_  50
#define THRESH_ 0.6f
#define OBJ_    5.0f
#define SPATIAL (NH_ * NW_)          // 1444
#define CPB     (NANC * SPATIAL)     // 7220 cells per batch
#define NCH     (5 + NCLS)           // 25 channels per anchor

// Scratch for per-GT data (no allocations allowed -> __device__ globals)
__device__ int   g_nvalid[NBATCH];
__device__ float g_gtbox[NBATCH * MAXB_ * 4];   // gx, gy, gw, gh (grid units)
__device__ int   g_gcell[NBATCH * MAXB_];       // local cell index (a*NH+gj)*NW+gi
__device__ float g_t6[NBATCH * MAXB_ * 6];      // tx, ty, tw, th, tconf, tcls

__device__ __forceinline__ float sigm(float v) { return 1.0f / (1.0f + __expf(-v)); }

__device__ __forceinline__ float iou_centered(float x1, float y1, float w1, float h1,
                                              float x2, float y2, float w2, float h2) {
    float mx = fminf(x1 - 0.5f * w1, x2 - 0.5f * w2);
    float Mx = fmaxf(x1 + 0.5f * w1, x2 + 0.5f * w2);
    float my = fminf(y1 - 0.5f * h1, y2 - 0.5f * h2);
    float My = fmaxf(y1 + 0.5f * h1, y2 + 0.5f * h2);
    float cw = w1 + w2 - (Mx - mx);
    float ch = h1 + h2 - (My - my);
    float inter = (cw <= 0.0f || ch <= 0.0f) ? 0.0f : cw * ch;
    float uni = w1 * h1 + w2 * h2 - inter;
    return inter / uni;
}

// ---------------------------------------------------------------------------
// Prep kernel: one block per batch. Parses target list, computes per-GT best
// anchor, target regression values, and tconf (IoU of GT vs prediction at the
// assigned cell). Also zeroes the output scalar.
// ---------------------------------------------------------------------------
__global__ void region_prep_kernel(const float* __restrict__ out,
                                   const float* __restrict__ tgt,
                                   const float* __restrict__ anchors,
                                   float* __restrict__ res) {
    int b = blockIdx.x;
    int t = threadIdx.x;
    __shared__ int s_nv;
    if (t == 0) {
        if (b == 0) res[0] = 0.0f;
        int nv = 0;
        const float* tb = tgt + b * MAXB_ * 5;
        for (int k = 0; k < MAXB_; k++) {
            if (tb[k * 5 + 1] == 0.0f) break;
            nv++;
        }
        g_nvalid[b] = nv;
        s_nv = nv;
    }
    __syncthreads();
    if (t >= s_nv) return;

    const float* tp = tgt + (b * MAXB_ + t) * 5;
    float cls = tp[0];
    float gx = tp[1] * NW_;
    float gy = tp[2] * NH_;
    float gw = tp[3] * NW_;
    float gh = tp[4] * NH_;

    // Best anchor by (w,h)-only IoU, first-index-wins ties (matches argmax)
    int bn = 0;
    float best = -1.0f;
    for (int a = 0; a < NANC; a++) {
        float aw = anchors[2 * a], ah = anchors[2 * a + 1];
        float inter = fminf(aw, gw) * fminf(ah, gh);
        float uni = aw * ah + gw * gh - inter;
        float r = inter / uni;
        if (r > best) { best = r; bn = a; }
    }
    int gi = min(max((int)gx, 0), NW_ - 1);
    int gj = min(max((int)gy, 0), NH_ - 1);
    int local = (bn * NH_ + gj) * NW_ + gi;

    // Prediction at the assigned cell
    const float* op = out + ((size_t)(b * NANC + bn)) * NCH * SPATIAL + gj * NW_ + gi;
    float aw = anchors[2 * bn], ah = anchors[2 * bn + 1];
    float px = sigm(op[0]) + (float)gi;
    float py = sigm(op[SPATIAL]) + (float)gj;
    float pw = expf(op[2 * SPATIAL]) * aw;
    float ph = expf(op[3 * SPATIAL]) * ah;
    float tconf = iou_centered(gx, gy, gw, gh, px, py, pw, ph);

    int idx = b * MAXB_ + t;
    g_gtbox[idx * 4 + 0] = gx;
    g_gtbox[idx * 4 + 1] = gy;
    g_gtbox[idx * 4 + 2] = gw;
    g_gtbox[idx * 4 + 3] = gh;
    g_gcell[idx] = local;
    g_t6[idx * 6 + 0] = gx - (float)gi;
    g_t6[idx * 6 + 1] = gy - (float)gj;
    g_t6[idx * 6 + 2] = logf(gw / aw);
    g_t6[idx * 6 + 3] = logf(gh / ah);
    g_t6[idx * 6 + 4] = tconf;
    g_t6[idx * 6 + 5] = cls;
}

// ---------------------------------------------------------------------------
// Main kernel: grid (29, 64), 256 threads. One thread per anchor-cell.
// Stages the batch's GT list in SMEM; inner loop is division-free
// (tests inter > THRESH*union instead of computing IoU).
// ---------------------------------------------------------------------------
__global__ void region_loss_kernel(const float* __restrict__ out,
                                   const float* __restrict__ anchors,
                                   float* __restrict__ res) {
    int b = blockIdx.y;
    int local = blockIdx.x * blockDim.x + threadIdx.x;

    __shared__ float s_box[MAXB_ * 4];
    __shared__ int   s_cell[MAXB_];
    __shared__ float s_t6[MAXB_ * 6];
    __shared__ int   s_nv;

    if (threadIdx.x == 0) s_nv = g_nvalid[b];
    __syncthreads();
    int nv = s_nv;
    if (threadIdx.x < nv) {
        int idx = b * MAXB_ + threadIdx.x;
        s_box[threadIdx.x * 4 + 0] = g_gtbox[idx * 4 + 0];
        s_box[threadIdx.x * 4 + 1] = g_gtbox[idx * 4 + 1];
        s_box[threadIdx.x * 4 + 2] = g_gtbox[idx * 4 + 2];
        s_box[threadIdx.x * 4 + 3] = g_gtbox[idx * 4 + 3];
        s_cell[threadIdx.x] = g_gcell[idx];
        #pragma unroll
        for (int q = 0; q < 6; q++) s_t6[threadIdx.x * 6 + q] = g_t6[idx * 6 + q];
    }
    __syncthreads();

    float contrib = 0.0f;
    if (local < CPB) {
        int a = local / SPATIAL;
        int rem = local - a * SPATIAL;
        int j = rem / NW_;
        int i = rem - j * NW_;

        const float* op = out + ((size_t)(b * NANC + a)) * NCH * SPATIAL + rem;
        float o0 = op[0];
        float o1 = op[SPATIAL];
        float o2 = op[2 * SPATIAL];
        float o3 = op[3 * SPATIAL];
        float o4 = op[4 * SPATIAL];

        float x = sigm(o0), y = sigm(o1), conf = sigm(o4);
        float aw = anchors[2 * a], ah = anchors[2 * a + 1];
        float px = x + (float)i;
        float py = y + (float)j;
        float pw = __expf(o2) * aw;
        float ph = __expf(o3) * ah;
        float parea = pw * ph;
        float pxl = px - 0.5f * pw, pxr = px + 0.5f * pw;
        float pyl = py - 0.5f * ph, pyr = py + 0.5f * ph;

        bool over = false;
        int slot = -1;
        for (int t = 0; t < nv; t++) {
            float gx = s_box[t * 4 + 0], gy = s_box[t * 4 + 1];
            float gw = s_box[t * 4 + 2], gh = s_box[t * 4 + 3];
            float mx = fminf(pxl, gx - 0.5f * gw);
            float Mx = fmaxf(pxr, gx + 0.5f * gw);
            float my = fminf(pyl, gy - 0.5f * gh);
            float My = fmaxf(pyr, gy + 0.5f * gh);
            float cw = pw + gw - (Mx - mx);
            float ch = ph + gh - (My - my);
            if (cw > 0.0f && ch > 0.0f) {
                float inter = cw * ch;
                float uni = parea + gw * gh - inter;
                over = over || (inter > THRESH_ * uni);   // iou > THRESH, no divide
            }
            if (s_cell[t] == local) slot = t;
        }

        float cmask = over ? 0.0f : 1.0f;   // NOOBJ = 1
        float tx = 0.5f, ty = 0.5f, tw = 0.0f, th = 0.0f, tconf = 0.0f;
        if (slot >= 0) {
            cmask = OBJ_;
            tx    = s_t6[slot * 6 + 0];
            ty    = s_t6[slot * 6 + 1];
            tw    = s_t6[slot * 6 + 2];
            th    = s_t6[slot * 6 + 3];
            tconf = s_t6[slot * 6 + 4];
        }
        float dx = x - tx, dy = y - ty, dw = o2 - tw, dh = o3 - th, dc = conf - tconf;
        contrib = 0.5f * (dx * dx + dy * dy + dw * dw + dh * dh + cmask * dc * dc);

        if (slot >= 0) {
            // class NLL at this cell: -(logit[tcls] - logsumexp(logits))
            const float* cp = op + 5 * SPATIAL;
            float m = -1e30f;
            #pragma unroll
            for (int c = 0; c < NCLS; c++) m = fmaxf(m, cp[c * SPATIAL]);
            float s = 0.0f;
            #pragma unroll
            for (int c = 0; c < NCLS; c++) s += expf(cp[c * SPATIAL] - m);
            int tc = (int)s_t6[slot * 6 + 5];
            contrib += (m + logf(s)) - cp[tc * SPATIAL];
        }
    }

    // Block reduction + atomic accumulate
    __shared__ float red[256];
    red[threadIdx.x] = contrib;
    __syncthreads();
    for (int s = 128; s > 0; s >>= 1) {
        if (threadIdx.x < s) red[threadIdx.x] += red[threadIdx.x + s];
        __syncthreads();
    }
    if (threadIdx.x == 0) atomicAdd(res, red[0]);
}

extern "C" void kernel_launch(void* const* d_in, const int* in_sizes, int n_in,
                              void* d_out, int out_size) {
    const float* out = (const float*)d_in[0];
    const float* tgt = (const float*)d_in[1];
    const float* anc = (const float*)d_in[2];
    float* res = (float*)d_out;

    region_prep_kernel<<<NBATCH, 64>>>(out, tgt, anc, res);
    dim3 grid((CPB + 255) / 256, NBATCH);
    region_loss_kernel<<<grid, 256>>>(out, anc, res);
}

// round 2
// speedup vs baseline: 1.1047x; 1.1047x over previous
#include <cuda_runtime.h>
#include <math.h>

#define NCLS   20
#define NANC   5
#define NB_    64
#define NH_    38
#define NW_    38
#define MAXB_  50
#define SPATIAL 1444
#define CPB    7220            // NANC*SPATIAL
#define NGRP   (CPB / 4)       // 1805 groups of 4 cells
#define NCH    25
#define OBJ_   5.0f
#define K_     0.375f          // THRESH/(1+THRESH) = 0.6/1.6

// Scratch (__device__ globals: no allocations allowed)
__device__ int    g_nv[NB_];
__device__ float4 g_gt4[NB_ * MAXB_];   // gxl, gxr, gyl, gyr
__device__ float  g_g2[NB_ * MAXB_];    // 0.375 * gw * gh
__device__ float  g_corr[NB_];          // per-batch object-cell correction

__device__ __forceinline__ float sigm(float v) { return 1.0f / (1.0f + __expf(-v)); }

__device__ __forceinline__ float iou_full(float x1, float y1, float w1, float h1,
                                          float x2, float y2, float w2, float h2) {
    float cw = fminf(x1 + 0.5f * w1, x2 + 0.5f * w2) - fmaxf(x1 - 0.5f * w1, x2 - 0.5f * w2);
    float ch = fminf(y1 + 0.5f * h1, y2 + 0.5f * h2) - fmaxf(y1 - 0.5f * h1, y2 - 0.5f * h2);
    float inter = (cw <= 0.0f || ch <= 0.0f) ? 0.0f : cw * ch;
    float uni = w1 * h1 + w2 * h2 - inter;
    return inter / uni;
}

// ---------------------------------------------------------------------------
// Prep: one block per batch, 64 threads. Parses targets, stages GT boxes, and
// computes the per-batch correction term for object cells (obj - noobj),
// replicating the main kernel's math for the noobj part.
// ---------------------------------------------------------------------------
__global__ void region_prep(const float* __restrict__ out,
                            const float* __restrict__ tgt,
                            const float* __restrict__ anc,
                            float* __restrict__ res) {
    int b = blockIdx.x;
    int t = threadIdx.x;
    __shared__ int    s_nv;
    __shared__ int    s_cell[MAXB_];
    __shared__ float4 s_b4[MAXB_];
    __shared__ float  s_g2[MAXB_];
    __shared__ float  s_corr[64];
    s_corr[t] = 0.0f;

    if (t == 0) {
        if (b == 0) res[0] = 0.0f;
        int nv = 0;
        const float* tb = tgt + b * MAXB_ * 5;
        for (int k = 0; k < MAXB_; k++) {
            if (tb[k * 5 + 1] == 0.0f) break;
            nv++;
        }
        s_nv = nv;
        g_nv[b] = nv;
    }
    __syncthreads();
    int nv = s_nv;

    float gx = 0, gy = 0, gw = 0, gh = 0, cls = 0;
    int bn = 0, gi = 0, gj = 0, cell = -1;
    if (t < nv) {
        const float* tp = tgt + (b * MAXB_ + t) * 5;
        cls = tp[0];
        gx = tp[1] * NW_; gy = tp[2] * NH_;
        gw = tp[3] * NW_; gh = tp[4] * NH_;

        float best = -1.0f;
        for (int a = 0; a < NANC; a++) {
            float aw = anc[2 * a], ah = anc[2 * a + 1];
            float inter = fminf(aw, gw) * fminf(ah, gh);
            float uni = aw * ah + gw * gh - inter;
            float r = inter / uni;
            if (r > best) { best = r; bn = a; }
        }
        gi = min(max((int)gx, 0), NW_ - 1);
        gj = min(max((int)gy, 0), NH_ - 1);
        cell = (bn * NH_ + gj) * NW_ + gi;

        float4 b4 = make_float4(gx - 0.5f * gw, gx + 0.5f * gw,
                                gy - 0.5f * gh, gy + 0.5f * gh);
        s_cell[t] = cell;
        s_b4[t] = b4;
        s_g2[t] = K_ * gw * gh;
        g_gt4[b * MAXB_ + t] = b4;
        g_g2[b * MAXB_ + t] = K_ * gw * gh;
    }
    __syncthreads();

    if (t < nv) {
        // last-writer-wins dedup (matches .at[].set scatter semantics)
        bool winner = true;
        for (int u = t + 1; u < nv; u++)
            if (s_cell[u] == cell) winner = false;

        if (winner) {
            const float* op = out + ((size_t)(b * NANC + bn)) * NCH * SPATIAL
                              + gj * NW_ + gi;
            float o0 = op[0], o1 = op[SPATIAL], o2 = op[2 * SPATIAL],
                  o3 = op[3 * SPATIAL], o4 = op[4 * SPATIAL];
            float aw = anc[2 * bn], ah = anc[2 * bn + 1];

            // Same math as main kernel (noobj view of this cell)
            float x = sigm(o0), y = sigm(o1), conf = sigm(o4);
            float px = x + (float)gi, py = y + (float)gj;
            float pw = __expf(o2) * aw, ph = __expf(o3) * ah;
            float pxl = px - 0.5f * pw, pxr = px + 0.5f * pw;
            float pyl = py - 0.5f * ph, pyr = py + 0.5f * ph;
            float c0 = K_ * pw * ph;
            int over = 0;
            for (int u = 0; u < nv; u++) {
                float4 g = s_b4[u];
                float cw = fminf(pxr, g.y) - fmaxf(pxl, g.x);
                float ch = fminf(pyr, g.w) - fmaxf(pyl, g.z);
                if (cw > 0.0f && ch > 0.0f && cw * ch > c0 + s_g2[u]) over = 1;
            }
            float dxn = x - 0.5f, dyn = y - 0.5f;
            float noobj = 0.5f * (dxn * dxn + dyn * dyn + o2 * o2 + o3 * o3)
                        + (over ? 0.0f : 0.5f * conf * conf);

            // Object contribution
            float tx = gx - (float)gi, ty = gy - (float)gj;
            float tw = logf(gw / aw), th = logf(gh / ah);
            float tconf = iou_full(gx, gy, gw, gh, px, py, pw, ph);
            float dx = x - tx, dy = y - ty, dw = o2 - tw, dh = o3 - th,
                  dc = conf - tconf;
            float obj = 0.5f * (dx * dx + dy * dy + dw * dw + dh * dh
                                + OBJ_ * dc * dc);
            // class NLL
            const float* cp = op + 5 * SPATIAL;
            float m = -1e30f;
            #pragma unroll
            for (int c = 0; c < NCLS; c++) m = fmaxf(m, cp[c * SPATIAL]);
            float s = 0.0f;
            #pragma unroll
            for (int c = 0; c < NCLS; c++) s += expf(cp[c * SPATIAL] - m);
            int tc = (int)cls;
            obj += (m + logf(s)) - cp[tc * SPATIAL];

            s_corr[t] = obj - noobj;
        }
    }
    __syncthreads();
    // reduce corrections (64 threads)
    for (int sft = 32; sft > 0; sft >>= 1) {
        if (t < sft) s_corr[t] += s_corr[t + sft];
        __syncthreads();
    }
    if (t == 0) g_corr[b] = s_corr[0];
}

// ---------------------------------------------------------------------------
// Main: grid (8, 64), 256 threads, 4 cells per thread (vectorized LDG.128).
// Every cell treated as noobj; object correction pre-added from g_corr.
// ---------------------------------------------------------------------------
__global__ void __launch_bounds__(256)
region_main(const float* __restrict__ out,
            const float* __restrict__ anc,
            float* __restrict__ res) {
    int b = blockIdx.y;
    int group = blockIdx.x * 256 + threadIdx.x;

    __shared__ float4 s_b4[MAXB_];
    __shared__ float  s_g2[MAXB_];
    __shared__ int    s_nvs;
    if (threadIdx.x == 0) s_nvs = g_nv[b];
    __syncthreads();
    int nv = s_nvs;
    if (threadIdx.x < nv) {
        s_b4[threadIdx.x] = g_gt4[b * MAXB_ + threadIdx.x];
        s_g2[threadIdx.x] = g_g2[b * MAXB_ + threadIdx.x];
    }
    __syncthreads();

    float contrib = (blockIdx.x == 0 && threadIdx.x == 0) ? g_corr[b] : 0.0f;

    if (group < NGRP) {
        int base = group * 4;
        int a = base / SPATIAL;
        int rem = base - a * SPATIAL;
        int j0 = rem / NW_;
        int i0 = rem - j0 * NW_;

        const float* op = out + ((size_t)(b * NANC + a)) * NCH * SPATIAL + rem;
        float4 v0 = *(const float4*)(op);
        float4 v1 = *(const float4*)(op + SPATIAL);
        float4 v2 = *(const float4*)(op + 2 * SPATIAL);
        float4 v3 = *(const float4*)(op + 3 * SPATIAL);
        float4 v4 = *(const float4*)(op + 4 * SPATIAL);
        float o0[4] = {v0.x, v0.y, v0.z, v0.w};
        float o1[4] = {v1.x, v1.y, v1.z, v1.w};
        float o2[4] = {v2.x, v2.y, v2.z, v2.w};
        float o3[4] = {v3.x, v3.y, v3.z, v3.w};
        float o4[4] = {v4.x, v4.y, v4.z, v4.w};

        float aw = __ldg(&anc[2 * a]), ah = __ldg(&anc[2 * a + 1]);

        float pxl[4], pxr[4], pyl[4], pyr[4], c0[4], cf2[4];
        int over[4] = {0, 0, 0, 0};
        float basec = 0.0f;
        #pragma unroll
        for (int c = 0; c < 4; c++) {
            float x = sigm(o0[c]), y = sigm(o1[c]), conf = sigm(o4[c]);
            int ii = i0 + c, jj = j0;
            if (ii >= NW_) { ii -= NW_; jj++; }
            float px = x + (float)ii, py = y + (float)jj;
            float pw = __expf(o2[c]) * aw, ph = __expf(o3[c]) * ah;
            pxl[c] = px - 0.5f * pw; pxr[c] = px + 0.5f * pw;
            pyl[c] = py - 0.5f * ph; pyr[c] = py + 0.5f * ph;
            c0[c] = K_ * pw * ph;
            float dx = x - 0.5f, dy = y - 0.5f;
            basec += 0.5f * (dx * dx + dy * dy + o2[c] * o2[c] + o3[c] * o3[c]);
            cf2[c] = 0.5f * conf * conf;
        }

        for (int t = 0; t < nv; t++) {
            float4 g = s_b4[t];
            float g2 = s_g2[t];
            #pragma unroll
            for (int c = 0; c < 4; c++) {
                float cw = fminf(pxr[c], g.y) - fmaxf(pxl[c], g.x);
                float ch = fminf(pyr[c], g.w) - fmaxf(pyl[c], g.z);
                if (cw > 0.0f && ch > 0.0f && cw * ch > c0[c] + g2) over[c] = 1;
            }
        }
        contrib += basec;
        #pragma unroll
        for (int c = 0; c < 4; c++)
            if (!over[c]) contrib += cf2[c];
    }

    // warp reduce + cross-warp reduce + one atomic per block
    #pragma unroll
    for (int o = 16; o > 0; o >>= 1)
        contrib += __shfl_down_sync(0xFFFFFFFFu, contrib, o);
    __shared__ float wsum[8];
    if ((threadIdx.x & 31) == 0) wsum[threadIdx.x >> 5] = contrib;
    __syncthreads();
    if (threadIdx.x < 8) {
        float v = wsum[threadIdx.x];
        #pragma unroll
        for (int o = 4; o > 0; o >>= 1)
            v += __shfl_down_sync(0xFFu, v, o);
        if (threadIdx.x == 0) atomicAdd(res, v);
    }
}

extern "C" void kernel_launch(void* const* d_in, const int* in_sizes, int n_in,
                              void* d_out, int out_size) {
    const float* out = (const float*)d_in[0];
    const float* tgt = (const float*)d_in[1];
    const float* anc = (const float*)d_in[2];
    float* res = (float*)d_out;

    region_prep<<<NB_, 64>>>(out, tgt, anc, res);
    dim3 grid((NGRP + 255) / 256, NB_);
    region_main<<<grid, 256>>>(out, anc, res);
}

// round 3
// speedup vs baseline: 1.2765x; 1.1555x over previous
#include <cuda_runtime.h>
#include <math.h>

#define NCLS   20
#define NANC   5
#define NB_    64
#define NH_    38
#define NW_    38
#define MAXB_  50
#define SPATIAL 1444
#define CPB    7220            // NANC*SPATIAL
#define NGRP   (CPB / 4)       // 1805 groups of 4 cells
#define NCH    25
#define OBJ_   5.0f
#define K_     0.375f          // THRESH/(1+THRESH) = 0.6/1.6
#define GRIDX  8
#define NBLK   (GRIDX * NB_)   // 512 blocks total

// Last-block aggregation state (zero-initialized at load; reset each call)
__device__ float        g_acc = 0.0f;
__device__ unsigned int g_cnt = 0;

__device__ __forceinline__ float sigm(float v) { return 1.0f / (1.0f + __expf(-v)); }

__device__ __forceinline__ float iou_full(float x1, float y1, float w1, float h1,
                                          float x2, float y2, float w2, float h2) {
    float cw = fminf(x1 + 0.5f * w1, x2 + 0.5f * w2) - fmaxf(x1 - 0.5f * w1, x2 - 0.5f * w2);
    float ch = fminf(y1 + 0.5f * h1, y2 + 0.5f * h2) - fmaxf(y1 - 0.5f * h1, y2 - 0.5f * h2);
    float inter = (cw <= 0.0f || ch <= 0.0f) ? 0.0f : cw * ch;
    float uni = w1 * h1 + w2 * h2 - inter;
    return inter / uni;
}

// One fused kernel. grid = (GRIDX, NB_), 256 threads.
// Each block: parallel-parse its batch's targets -> shared GT list (padded to
// multiple of 4 with dummies); block x==0 also computes the object-cell
// correction; then 4 cells/thread noobj loop; last block writes res.
__global__ void __launch_bounds__(256)
region_fused(const float* __restrict__ out,
             const float* __restrict__ tgt,
             const float* __restrict__ anc,
             float* __restrict__ res) {
    const int b = blockIdx.y;
    const int tid = threadIdx.x;

    __shared__ int    s_nv;
    __shared__ float4 s_b4[MAXB_ + 4];
    __shared__ float  s_g2[MAXB_ + 4];
    __shared__ int    s_cell[MAXB_];

    if (tid == 0) s_nv = MAXB_;
    __syncthreads();

    // Parallel parse: first index with tgt[:,1]==0 terminates the list
    if (tid < MAXB_) {
        float tp1 = tgt[b * MAXB_ * 5 + tid * 5 + 1];
        if (tp1 == 0.0f) atomicMin(&s_nv, tid);
    }
    __syncthreads();
    const int nv  = s_nv;
    const int nvp = (nv + 3) & ~3;

    float contrib = 0.0f;

    // Stage GT boxes (threads nv..nvp write dummies)
    float gx = 0, gy = 0, gw = 0, gh = 0, cls = 0;
    int bn = 0, gi = 0, gj = 0;
    if (tid < nvp) {
        if (tid < nv) {
            const float* tp = tgt + (b * MAXB_ + tid) * 5;
            cls = tp[0];
            gx = tp[1] * NW_; gy = tp[2] * NH_;
            gw = tp[3] * NW_; gh = tp[4] * NH_;
            float best = -1.0f;
            #pragma unroll
            for (int a = 0; a < NANC; a++) {
                float aw = __ldg(&anc[2 * a]), ah = __ldg(&anc[2 * a + 1]);
                float inter = fminf(aw, gw) * fminf(ah, gh);
                float r = inter / (aw * ah + gw * gh - inter);
                if (r > best) { best = r; bn = a; }
            }
            gi = min(max((int)gx, 0), NW_ - 1);
            gj = min(max((int)gy, 0), NH_ - 1);
            s_cell[tid] = (bn * NH_ + gj) * NW_ + gi;
            s_b4[tid] = make_float4(gx - 0.5f * gw, gx + 0.5f * gw,
                                    gy - 0.5f * gh, gy + 0.5f * gh);
            s_g2[tid] = K_ * gw * gh;
        } else {
            s_b4[tid] = make_float4(1e30f, -1e30f, 1e30f, -1e30f);
            s_g2[tid] = 1e30f;   // fma(0,0,-1e30) -> never triggers
        }
    }
    __syncthreads();

    // Object-cell correction (block x==0 only), added into this thread's contrib
    if (blockIdx.x == 0 && tid < nv) {
        bool winner = true;            // last-writer-wins scatter semantics
        for (int u = tid + 1; u < nv; u++)
            if (s_cell[u] == s_cell[tid]) winner = false;
        if (winner) {
            const float* op = out + ((size_t)(b * NANC + bn)) * NCH * SPATIAL
                              + gj * NW_ + gi;
            float o0 = op[0], o1 = op[SPATIAL], o2 = op[2 * SPATIAL],
                  o3 = op[3 * SPATIAL], o4 = op[4 * SPATIAL];
            float aw = __ldg(&anc[2 * bn]), ah = __ldg(&anc[2 * bn + 1]);

            float x = sigm(o0), y = sigm(o1), conf = sigm(o4);
            float px = x + (float)gi, py = y + (float)gj;
            float pw = __expf(o2) * aw, ph = __expf(o3) * ah;
            float pxl = px - 0.5f * pw, pxr = px + 0.5f * pw;
            float pyl = py - 0.5f * ph, pyr = py + 0.5f * ph;
            float c0 = K_ * pw * ph;
            int over = 0;
            for (int u = 0; u < nv; u++) {
                float4 g = s_b4[u];
                float cw = fminf(pxr, g.y) - fmaxf(pxl, g.x);
                float ch = fminf(pyr, g.w) - fmaxf(pyl, g.z);
                if (cw > 0.0f && ch > 0.0f && cw * ch > c0 + s_g2[u]) over = 1;
            }
            float dxn = x - 0.5f, dyn = y - 0.5f;
            float noobj = 0.5f * (dxn * dxn + dyn * dyn + o2 * o2 + o3 * o3)
                        + (over ? 0.0f : 0.5f * conf * conf);

            float tx = gx - (float)gi, ty = gy - (float)gj;
            float tw = logf(gw / aw), th = logf(gh / ah);
            float tconf = iou_full(gx, gy, gw, gh, px, py, pw, ph);
            float dx = x - tx, dy = y - ty, dw = o2 - tw, dh = o3 - th,
                  dc = conf - tconf;
            float obj = 0.5f * (dx * dx + dy * dy + dw * dw + dh * dh
                                + OBJ_ * dc * dc);
            const float* cp = op + 5 * SPATIAL;
            float mm = -1e30f;
            #pragma unroll
            for (int c = 0; c < NCLS; c++) mm = fmaxf(mm, cp[c * SPATIAL]);
            float s = 0.0f;
            #pragma unroll
            for (int c = 0; c < NCLS; c++) s += expf(cp[c * SPATIAL] - mm);
            obj += (mm + logf(s)) - cp[(int)cls * SPATIAL];

            contrib += obj - noobj;
        }
    }

    // Main noobj loop: 4 cells per thread, inner loop unrolled 4x over GTs
    const int group = blockIdx.x * 256 + tid;
    if (group < NGRP) {
        int base = group * 4;
        int a = base / SPATIAL;
        int rem = base - a * SPATIAL;
        int j0 = rem / NW_;
        int i0 = rem - j0 * NW_;

        const float* op = out + ((size_t)(b * NANC + a)) * NCH * SPATIAL + rem;
        float4 v0 = *(const float4*)(op);
        float4 v1 = *(const float4*)(op + SPATIAL);
        float4 v2 = *(const float4*)(op + 2 * SPATIAL);
        float4 v3 = *(const float4*)(op + 3 * SPATIAL);
        float4 v4 = *(const float4*)(op + 4 * SPATIAL);
        float o0[4] = {v0.x, v0.y, v0.z, v0.w};
        float o1[4] = {v1.x, v1.y, v1.z, v1.w};
        float o2[4] = {v2.x, v2.y, v2.z, v2.w};
        float o3[4] = {v3.x, v3.y, v3.z, v3.w};
        float o4[4] = {v4.x, v4.y, v4.z, v4.w};

        float aw = __ldg(&anc[2 * a]), ah = __ldg(&anc[2 * a + 1]);

        float pxl[4], pxr[4], pyl[4], pyr[4], c0[4], cf2[4], m[4];
        #pragma unroll
        for (int c = 0; c < 4; c++) {
            float x = sigm(o0[c]), y = sigm(o1[c]), conf = sigm(o4[c]);
            int ii = i0 + c, jj = j0;
            if (ii >= NW_) { ii -= NW_; jj++; }
            float px = x + (float)ii, py = y + (float)jj;
            float pw = __expf(o2[c]) * aw, ph = __expf(o3[c]) * ah;
            pxl[c] = px - 0.5f * pw; pxr[c] = px + 0.5f * pw;
            pyl[c] = py - 0.5f * ph; pyr[c] = py + 0.5f * ph;
            c0[c] = K_ * pw * ph;
            float dx = x - 0.5f, dy = y - 0.5f;
            contrib += 0.5f * (dx * dx + dy * dy + o2[c] * o2[c] + o3[c] * o3[c]);
            cf2[c] = 0.5f * conf * conf;
            m[c] = -1e30f;
        }

        for (int t = 0; t < nvp; t += 4) {
            #pragma unroll
            for (int u = 0; u < 4; u++) {
                float4 g = s_b4[t + u];
                float g2 = s_g2[t + u];
                #pragma unroll
                for (int c = 0; c < 4; c++) {
                    float cw = fmaxf(fminf(pxr[c], g.y) - fmaxf(pxl[c], g.x), 0.0f);
                    float ch = fmaxf(fminf(pyr[c], g.w) - fmaxf(pyl[c], g.z), 0.0f);
                    m[c] = fmaxf(m[c], fmaf(cw, ch, -g2));
                }
            }
        }
        #pragma unroll
        for (int c = 0; c < 4; c++)
            if (m[c] <= c0[c]) contrib += cf2[c];   // not over-threshold -> noobj conf
    }

    // Block reduce
    #pragma unroll
    for (int o = 16; o > 0; o >>= 1)
        contrib += __shfl_down_sync(0xFFFFFFFFu, contrib, o);
    __shared__ float wsum[8];
    if ((tid & 31) == 0) wsum[tid >> 5] = contrib;
    __syncthreads();
    if (tid == 0) {
        float v = 0.0f;
        #pragma unroll
        for (int q = 0; q < 8; q++) v += wsum[q];
        atomicAdd(&g_acc, v);
        __threadfence();
        unsigned prev = atomicAdd(&g_cnt, 1u);
        if (prev == NBLK - 1) {
            // all block sums visible (fence before each counter increment)
            float total = atomicAdd(&g_acc, 0.0f);
            res[0] = total;
            g_acc = 0.0f;          // reset for next graph replay
            __threadfence();
            g_cnt = 0u;
        }
    }
}

extern "C" void kernel_launch(void* const* d_in, const int* in_sizes, int n_in,
                              void* d_out, int out_size) {
    const float* out = (const float*)d_in[0];
    const float* tgt = (const float*)d_in[1];
    const float* anc = (const float*)d_in[2];
    float* res = (float*)d_out;

    dim3 grid(GRIDX, NB_);
    region_fused<<<grid, 256>>>(out, tgt, anc, res);
}